// round 1
// baseline (speedup 1.0000x reference)
#include <cuda_runtime.h>
#include <cuda_bf16.h>

// Scratch: [b*3 + {0:inter, 1:psum, 2:tsum}] for b in 0..B-1 (B<=8 supported)
__device__ double g_acc[24];

__global__ void zero_acc_kernel() {
    if (threadIdx.x < 24) g_acc[threadIdx.x] = 0.0;
}

template <int BLOCK>
__global__ void dice_reduce_kernel(const float4* __restrict__ pred,
                                   const float4* __restrict__ tgt,
                                   int n4_per_sample,
                                   int blocks_per_sample) {
    const int b   = blockIdx.x / blocks_per_sample;
    const int blk = blockIdx.x % blocks_per_sample;

    const float4* __restrict__ p4 = pred + (size_t)b * n4_per_sample;
    const float4* __restrict__ t4 = tgt  + (size_t)b * n4_per_sample;

    float s_pt = 0.f, s_p = 0.f, s_t = 0.f;

    const int stride = blocks_per_sample * BLOCK;
    for (int i = blk * BLOCK + threadIdx.x; i < n4_per_sample; i += stride) {
        float4 pv = p4[i];
        float4 tv = t4[i];

        float sp0 = 1.0f / (1.0f + __expf(-pv.x));
        float sp1 = 1.0f / (1.0f + __expf(-pv.y));
        float sp2 = 1.0f / (1.0f + __expf(-pv.z));
        float sp3 = 1.0f / (1.0f + __expf(-pv.w));

        s_p  += (sp0 + sp1) + (sp2 + sp3);
        s_t  += (tv.x + tv.y) + (tv.z + tv.w);
        s_pt += sp0 * tv.x + sp1 * tv.y + sp2 * tv.z + sp3 * tv.w;
    }

    // Warp reduce
    #pragma unroll
    for (int off = 16; off > 0; off >>= 1) {
        s_pt += __shfl_down_sync(0xffffffffu, s_pt, off);
        s_p  += __shfl_down_sync(0xffffffffu, s_p,  off);
        s_t  += __shfl_down_sync(0xffffffffu, s_t,  off);
    }

    __shared__ float sh_pt[BLOCK / 32];
    __shared__ float sh_p [BLOCK / 32];
    __shared__ float sh_t [BLOCK / 32];

    const int lane = threadIdx.x & 31;
    const int wid  = threadIdx.x >> 5;
    if (lane == 0) { sh_pt[wid] = s_pt; sh_p[wid] = s_p; sh_t[wid] = s_t; }
    __syncthreads();

    if (wid == 0) {
        constexpr int NW = BLOCK / 32;
        float v_pt = (lane < NW) ? sh_pt[lane] : 0.f;
        float v_p  = (lane < NW) ? sh_p [lane] : 0.f;
        float v_t  = (lane < NW) ? sh_t [lane] : 0.f;
        #pragma unroll
        for (int off = NW / 2; off > 0; off >>= 1) {
            v_pt += __shfl_down_sync(0xffffffffu, v_pt, off);
            v_p  += __shfl_down_sync(0xffffffffu, v_p,  off);
            v_t  += __shfl_down_sync(0xffffffffu, v_t,  off);
        }
        if (lane == 0) {
            atomicAdd(&g_acc[b * 3 + 0], (double)v_pt);
            atomicAdd(&g_acc[b * 3 + 1], (double)v_p);
            atomicAdd(&g_acc[b * 3 + 2], (double)v_t);
        }
    }
}

__global__ void dice_finalize_kernel(const float* __restrict__ weight,
                                     float* __restrict__ out, int B) {
    if (threadIdx.x == 0 && blockIdx.x == 0) {
        double total = 0.0;
        const double smooth = 1.0;
        for (int b = 0; b < B; ++b) {
            double w     = (double)weight[b];
            double inter = g_acc[b * 3 + 0] * w;
            double psum  = g_acc[b * 3 + 1] * w;
            double tsum  = g_acc[b * 3 + 2] * w;
            double dice  = (2.0 * inter + smooth) / (psum + tsum + smooth);
            total += 1.0 - dice;
        }
        out[0] = (float)(total / (double)B);
    }
}

extern "C" void kernel_launch(void* const* d_in, const int* in_sizes, int n_in,
                              void* d_out, int out_size) {
    const float* pred   = (const float*)d_in[0];
    const float* target = (const float*)d_in[1];
    const float* weight = (const float*)d_in[2];
    float* out = (float*)d_out;

    const int B = in_sizes[2];               // 3
    const int n_per = in_sizes[0] / B;       // 192^3 = 7,077,888 (divisible by 4)
    const int n4_per = n_per / 4;

    constexpr int BLOCK = 256;
    const int blocks_per_sample = 512;       // 3*512 = 1536 blocks total

    zero_acc_kernel<<<1, 32>>>();
    dice_reduce_kernel<BLOCK><<<B * blocks_per_sample, BLOCK>>>(
        (const float4*)pred, (const float4*)target, n4_per, blocks_per_sample);
    dice_finalize_kernel<<<1, 32>>>(weight, out, B);
}